// round 11
// baseline (speedup 1.0000x reference)
#include <cuda_runtime.h>

#define NAO   14
#define NAO2  196
#define SPB   32            // samples per block
#define XST   33            // smem word stride (odd -> conflict-free)
#define NTHR  256
#define NWARP 8
#define SMEM_BYTES (2 * NAO2 * XST * 4)

// ===========================================================================
// Compile-time construction of the CG / Wigner-3j sparse matrix, organised
// as 36 orbital-pair units with register-cached input columns.
// ===========================================================================
namespace ct {

constexpr double fct(int n) { double r = 1.0; for (int i = 2; i <= n; ++i) r *= i; return r; }

constexpr double csqrt(double v)
{
    if (v <= 0.0) return 0.0;
    double x = v < 1.0 ? 1.0 : v;
    for (int i = 0; i < 100; ++i) {
        double nx = 0.5 * (x + v / x);
        if (nx == x) break;
        x = nx;
    }
    return x;
}

constexpr double su2cg(int j1, int m1, int j2, int m2, int j3, int m3)
{
    if (m3 != m1 + m2) return 0.0;
    int vmin = -j1 + j2 + m3; if (-j1 + m1 > vmin) vmin = -j1 + m1; if (0 > vmin) vmin = 0;
    int vmax = j2 + j3 + m1; if (j3 - j1 + j2 < vmax) vmax = j3 - j1 + j2; if (j3 + m3 < vmax) vmax = j3 + m3;
    double c = csqrt((2.0 * j3 + 1) * fct(j3 + j1 - j2) * fct(j3 - j1 + j2) *
                     fct(j1 + j2 - j3) * fct(j3 + m3) * fct(j3 - m3) /
                     (fct(j1 + j2 + j3 + 1) * fct(j1 - m1) * fct(j1 + m1) *
                      fct(j2 - m2) * fct(j2 + m2)));
    double s = 0.0;
    for (int v = vmin; v <= vmax; ++v) {
        double sign = ((v + j2 + m2) & 1) ? -1.0 : 1.0;
        s += sign * fct(j2 + j3 + m1 - v) * fct(j1 - m1 + v) /
             (fct(v) * fct(j3 - j1 + j2 - v) * fct(j3 + m3 - v) * fct(v + j1 - j2 - m3));
    }
    return c * s;
}

struct CD { double re; double im; };
constexpr CD cmul(CD a, CD b) { return {a.re * b.re - a.im * b.im, a.re * b.im + a.im * b.re}; }
constexpr bool czero(CD a) { return a.re == 0.0 && a.im == 0.0; }

constexpr void qmat(int l, CD* q)
{
    int n = 2 * l + 1;
    for (int i = 0; i < n * n; ++i) q[i] = {0.0, 0.0};
    double is2 = csqrt(0.5);
    for (int m = -l; m < 0; ++m) {
        q[(l + m) * n + (l - m)] = {is2, 0.0};
        q[(l + m) * n + (l + m)] = {0.0, -is2};
    }
    q[l * n + l] = {1.0, 0.0};
    for (int m = 1; m <= l; ++m) {
        double sg = (m & 1) ? -1.0 : 1.0;
        q[(l + m) * n + (l + m)] = {sg * is2, 0.0};
        q[(l + m) * n + (l - m)] = {0.0, sg * is2};
    }
    CD f{1.0, 0.0};
    const CD mi{0.0, -1.0};
    for (int t = 0; t < l; ++t) f = cmul(f, mi);
    for (int i = 0; i < n * n; ++i) q[i] = cmul(q[i], f);
}

constexpr void wigner3j(int l1, int l2, int l3, double* outv)
{
    const int n1 = 2 * l1 + 1, n2 = 2 * l2 + 1, n3 = 2 * l3 + 1;
    double csu2[225] = {};
    for (int m1 = -l1; m1 <= l1; ++m1)
        for (int m2 = -l2; m2 <= l2; ++m2) {
            int m3 = m1 + m2;
            if (m3 >= -l3 && m3 <= l3)
                csu2[((l1 + m1) * n2 + (l2 + m2)) * n3 + (l3 + m3)] =
                    su2cg(l1, m1, l2, m2, l3, m3);
        }
    CD q1[81] = {}, q2[25] = {}, q3[25] = {};
    qmat(l1, q1); qmat(l2, q2); qmat(l3, q3);

    CD cc[225] = {};
    for (int i = 0; i < n1 * n2 * n3; ++i) cc[i] = {0.0, 0.0};
    for (int i = 0; i < n1; ++i)
        for (int k = 0; k < n2; ++k)
            for (int n = 0; n < n3; ++n) {
                double s = csu2[(i * n2 + k) * n3 + n];
                if (s == 0.0) continue;
                for (int a = 0; a < n1; ++a) {
                    CD qa = q1[i * n1 + a];
                    if (czero(qa)) continue;
                    for (int b = 0; b < n2; ++b) {
                        CD qb = q2[k * n2 + b];
                        if (czero(qb)) continue;
                        CD qab = cmul(qa, qb);
                        qab.re *= s; qab.im *= s;
                        for (int c = 0; c < n3; ++c) {
                            CD q3c = q3[n * n3 + c];
                            if (czero(q3c)) continue;
                            CD cj{q3c.re, -q3c.im};
                            CD add = cmul(qab, cj);
                            cc[(a * n2 + b) * n3 + c].re += add.re;
                            cc[(a * n2 + b) * n3 + c].im += add.im;
                        }
                    }
                }
            }
    double nre = 0.0, nim = 0.0;
    for (int i = 0; i < n1 * n2 * n3; ++i) {
        nre += cc[i].re * cc[i].re;
        nim += cc[i].im * cc[i].im;
    }
    bool useRe = csqrt(nre) >= csqrt(nim);
    double nn = csqrt(useRe ? nre : nim);
    for (int i = 0; i < n1 * n2 * n3; ++i)
        outv[i] = (useRe ? cc[i].re : cc[i].im) / nn;
}

// -------------------- pair-unit table --------------------
struct PTab {
    int   ncols[36];          // columns per pair (= nr*nc)
    int   coloff[36][25];     // xs word offsets (col * XST)
    int   nrows[36];          // output rows per pair
    int   rowid[36][25];      // natural output row ids
    int   nterm[36][25];
    float tc[36][25][25];     // coefficients
    int   tk[36][25][25];     // local column index
    int   wp[NWARP][12];      // warp -> pair list
    int   nwp[NWARP];
};

constexpr PTab build()
{
    PTab T{};
    const int LSh[6]  = {0, 0, 0, 1, 1, 2};
    const int IDXC[NAO] = {0, 1, 2, 5, 3, 4, 8, 6, 7, 11, 13, 9, 12, 10};
    int inv[NAO] = {};
    for (int i = 0; i < NAO; ++i) inv[IDXC[i]] = i;

    // enumerate blocks (original order) with pair id
    int brs[56] = {}, bnr[56] = {}, bcs[56] = {}, bnc[56] = {}, bL[56] = {}, bpar[56] = {}, bco[56] = {}, bp[56] = {};
    double cg[2120] = {};
    int nb = 0, cgo = 0, rs = 0;
    for (int a = 0; a < 6; ++a) {
        int li = LSh[a], nr = 2 * li + 1, cs = 0;
        for (int b = 0; b < 6; ++b) {
            int lj = LSh[b], nc = 2 * lj + 1;
            int L0 = li > lj ? li - lj : lj - li;
            for (int L = L0; L <= li + lj; ++L) {
                brs[nb] = rs; bnr[nb] = nr; bcs[nb] = cs; bnc[nb] = nc;
                bL[nb] = L; bpar[nb] = ((li + lj) & 1) ? -1 : 1; bco[nb] = cgo;
                bp[nb] = a * 6 + b;
                wigner3j(L, li, lj, &cg[cgo]);
                cgo += (2 * L + 1) * nr * nc;
                ++nb;
            }
            cs += nc;
        }
        rs += nr;
    }

    // stable sort of blocks by (L, parity) -> output layout
    int perm[56] = {};
    for (int i = 0; i < 56; ++i) perm[i] = i;
    for (int i = 1; i < 56; ++i) {
        int p = perm[i]; int j = i - 1;
        while (j >= 0 && (bL[perm[j]] > bL[p] ||
               (bL[perm[j]] == bL[p] && bpar[perm[j]] > bpar[p]))) {
            perm[j + 1] = perm[j]; --j;
        }
        perm[j + 1] = p;
    }
    int outbase[56] = {};
    { int base = 0; for (int t = 0; t < 56; ++t) { outbase[perm[t]] = base; base += 2 * bL[perm[t]] + 1; } }

    // pair columns
    {
        int prs = 0;
        for (int a = 0; a < 6; ++a) {
            int li = LSh[a], nr = 2 * li + 1, pcs = 0;
            for (int b = 0; b < 6; ++b) {
                int lj = LSh[b], nc = 2 * lj + 1;
                int p = a * 6 + b;
                T.ncols[p] = nr * nc;
                for (int i = 0; i < nr; ++i)
                    for (int j = 0; j < nc; ++j) {
                        int col = inv[prs + i] * NAO + inv[pcs + j];
                        T.coloff[p][i * nc + j] = col * XST;
                    }
                pcs += nc;
            }
            prs += nr;
        }
    }

    // pair rows + terms
    for (int bi = 0; bi < nb; ++bi) {
        int p = bp[bi];
        int w = 2 * bL[bi] + 1;
        for (int k = 0; k < w; ++k) {
            int r  = outbase[bi] + k;
            int ri = T.nrows[p];
            T.rowid[p][ri] = r;
            int nt = 0;
            for (int i = 0; i < bnr[bi]; ++i)
                for (int j = 0; j < bnc[bi]; ++j) {
                    double v = cg[bco[bi] + (k * bnr[bi] + i) * bnc[bi] + j];
                    double av = v < 0 ? -v : v;
                    if (av > 1e-9) {
                        T.tc[p][ri][nt] = (float)v;
                        T.tk[p][ri][nt] = i * bnc[bi] + j;
                        ++nt;
                    }
                }
            T.nterm[p][ri] = nt;
            T.nrows[p]++;
        }
    }

    // pair cost & greedy warp assignment (sorted by cost desc, stable)
    int cost[36] = {};
    for (int p = 0; p < 36; ++p) {
        int c = T.ncols[p] + T.nrows[p];
        for (int r = 0; r < T.nrows[p]; ++r) c += T.nterm[p][r];
        cost[p] = c;
    }
    int order[36] = {};
    for (int i = 0; i < 36; ++i) order[i] = i;
    for (int i = 1; i < 36; ++i) {
        int p = order[i]; int j = i - 1;
        while (j >= 0 && cost[order[j]] < cost[p]) { order[j + 1] = order[j]; --j; }
        order[j + 1] = p;
    }
    int wcost[NWARP] = {};
    for (int i = 0; i < 36; ++i) {
        int best = 0;
        for (int w = 1; w < NWARP; ++w) if (wcost[w] < wcost[best]) best = w;
        T.wp[best][T.nwp[best]] = order[i];
        T.nwp[best]++;
        wcost[best] += cost[order[i]];
    }
    return T;
}

constexpr PTab PT = build();

} // namespace ct

// ===========================================================================
// Fully-unrolled compute. Every table access is hoisted into a constexpr
// local so the host-side constexpr object is never referenced from device
// code (only compile-time immediates survive).
// ===========================================================================
template<int P, int K>
__device__ __forceinline__ void load_cols(const float* xl, float* v)
{
    constexpr int o  = ct::PT.coloff[P][K];
    constexpr int nc = ct::PT.ncols[P];
    v[K] = xl[o];
    if constexpr (K + 1 < nc) load_cols<P, K + 1>(xl, v);
}

template<int P, int R, int T>
__device__ __forceinline__ void row_terms(const float* v, float& a)
{
    constexpr float c  = ct::PT.tc[P][R][T];
    constexpr int   k  = ct::PT.tk[P][R][T];
    constexpr int   nt = ct::PT.nterm[P][R];
    a = fmaf(c, v[k], a);
    if constexpr (T + 1 < nt) row_terms<P, R, T + 1>(v, a);
}

template<int P, int R>
__device__ __forceinline__ void pair_rows(const float* v, float* os, int lane)
{
    constexpr int nt = ct::PT.nterm[P][R];
    constexpr int ro = ct::PT.rowid[P][R] * XST;
    constexpr int nr = ct::PT.nrows[P];
    float a = 0.f;
    if constexpr (nt > 0) row_terms<P, R, 0>(v, a);
    os[ro + lane] = a;
    if constexpr (R + 1 < nr) pair_rows<P, R + 1>(v, os, lane);
}

template<int P>
__device__ __forceinline__ void pair_run(const float* xl, float* os, int lane)
{
    float v[25];
    load_cols<P, 0>(xl, v);
    pair_rows<P, 0>(v, os, lane);
}

template<int W, int I>
__device__ __forceinline__ void warp_run(const float* xl, float* os, int lane)
{
    constexpr int p  = ct::PT.wp[W][I];
    constexpr int np = ct::PT.nwp[W];
    pair_run<p>(xl, os, lane);
    if constexpr (I + 1 < np) warp_run<W, I + 1>(xl, os, lane);
}

__global__ void __launch_bounds__(NTHR, 4)
te_kernel(const float* __restrict__ x, float* __restrict__ out, int nsamp)
{
    extern __shared__ float sm[];
    float* xs = sm;                  // [196][33]  element-major, sample fastest
    float* os = sm + NAO2 * XST;     // [196][33]

    const int tid = threadIdx.x;
    const int n0  = blockIdx.x * SPB;
    int valid = nsamp - n0; if (valid > SPB) valid = SPB;
    const int total = valid * NAO2;

    // ---- stage in: scalar LDG, conflict-free STS (lane stride 33 = 1 mod 32)
    {
        const float* src = x + (long long)n0 * NAO2;
        int s = tid / NAO2, e = tid - (tid / NAO2) * NAO2;
        #pragma unroll 4
        for (int f = tid; f < total; f += NTHR) {
            xs[e * XST + s] = src[f];
            e += 60; s += 1;                    // 256 = 196 + 60
            if (e >= NAO2) { e -= NAO2; s += 1; }
        }
    }
    __syncthreads();

    // ---- pair-structured, fully-unrolled sparse matvec ----
    {
        const int wid  = tid >> 5;
        const int lane = tid & 31;
        const float* xl = xs + lane;
        switch (wid) {
            case 0:  warp_run<0, 0>(xl, os, lane); break;
            case 1:  warp_run<1, 0>(xl, os, lane); break;
            case 2:  warp_run<2, 0>(xl, os, lane); break;
            case 3:  warp_run<3, 0>(xl, os, lane); break;
            case 4:  warp_run<4, 0>(xl, os, lane); break;
            case 5:  warp_run<5, 0>(xl, os, lane); break;
            case 6:  warp_run<6, 0>(xl, os, lane); break;
            default: warp_run<7, 0>(xl, os, lane); break;
        }
    }
    __syncthreads();

    // ---- stage out: conflict-free LDS, scalar STG ----
    {
        float* dst = out + (long long)n0 * NAO2;
        int s = tid / NAO2, e = tid - (tid / NAO2) * NAO2;
        #pragma unroll 4
        for (int f = tid; f < total; f += NTHR) {
            dst[f] = os[e * XST + s];
            e += 60; s += 1;
            if (e >= NAO2) { e -= NAO2; s += 1; }
        }
    }
}

extern "C" void kernel_launch(void* const* d_in, const int* in_sizes, int n_in,
                              void* d_out, int out_size)
{
    (void)n_in; (void)out_size;
    const float* x  = (const float*)d_in[0];
    float*      out = (float*)d_out;
    const int nsamp = in_sizes[0] / NAO2;

    cudaFuncSetAttribute(te_kernel, cudaFuncAttributeMaxDynamicSharedMemorySize, SMEM_BYTES);

    const int grid = (nsamp + SPB - 1) / SPB;
    te_kernel<<<grid, NTHR, SMEM_BYTES>>>(x, out, nsamp);
}

// round 12
// speedup vs baseline: 1.2801x; 1.2801x over previous
#include <cuda_runtime.h>

#define NAO   14
#define NAO2  196
#define SPB   32            // samples per block
#define XST   33            // smem word stride (odd -> conflict-free)
#define NTHR  256
#define NWARP 8
#define SMEM_BYTES (2 * NAO2 * XST * 4)

// ===========================================================================
// Compile-time construction of the CG / Wigner-3j sparse matrix, organised
// as 36 orbital-pair units with register-cached input columns.
// ===========================================================================
namespace ct {

constexpr double fct(int n) { double r = 1.0; for (int i = 2; i <= n; ++i) r *= i; return r; }

constexpr double csqrt(double v)
{
    if (v <= 0.0) return 0.0;
    double x = v < 1.0 ? 1.0 : v;
    for (int i = 0; i < 100; ++i) {
        double nx = 0.5 * (x + v / x);
        if (nx == x) break;
        x = nx;
    }
    return x;
}

constexpr double su2cg(int j1, int m1, int j2, int m2, int j3, int m3)
{
    if (m3 != m1 + m2) return 0.0;
    int vmin = -j1 + j2 + m3; if (-j1 + m1 > vmin) vmin = -j1 + m1; if (0 > vmin) vmin = 0;
    int vmax = j2 + j3 + m1; if (j3 - j1 + j2 < vmax) vmax = j3 - j1 + j2; if (j3 + m3 < vmax) vmax = j3 + m3;
    double c = csqrt((2.0 * j3 + 1) * fct(j3 + j1 - j2) * fct(j3 - j1 + j2) *
                     fct(j1 + j2 - j3) * fct(j3 + m3) * fct(j3 - m3) /
                     (fct(j1 + j2 + j3 + 1) * fct(j1 - m1) * fct(j1 + m1) *
                      fct(j2 - m2) * fct(j2 + m2)));
    double s = 0.0;
    for (int v = vmin; v <= vmax; ++v) {
        double sign = ((v + j2 + m2) & 1) ? -1.0 : 1.0;
        s += sign * fct(j2 + j3 + m1 - v) * fct(j1 - m1 + v) /
             (fct(v) * fct(j3 - j1 + j2 - v) * fct(j3 + m3 - v) * fct(v + j1 - j2 - m3));
    }
    return c * s;
}

struct CD { double re; double im; };
constexpr CD cmul(CD a, CD b) { return {a.re * b.re - a.im * b.im, a.re * b.im + a.im * b.re}; }
constexpr bool czero(CD a) { return a.re == 0.0 && a.im == 0.0; }

constexpr void qmat(int l, CD* q)
{
    int n = 2 * l + 1;
    for (int i = 0; i < n * n; ++i) q[i] = {0.0, 0.0};
    double is2 = csqrt(0.5);
    for (int m = -l; m < 0; ++m) {
        q[(l + m) * n + (l - m)] = {is2, 0.0};
        q[(l + m) * n + (l + m)] = {0.0, -is2};
    }
    q[l * n + l] = {1.0, 0.0};
    for (int m = 1; m <= l; ++m) {
        double sg = (m & 1) ? -1.0 : 1.0;
        q[(l + m) * n + (l + m)] = {sg * is2, 0.0};
        q[(l + m) * n + (l - m)] = {0.0, sg * is2};
    }
    CD f{1.0, 0.0};
    const CD mi{0.0, -1.0};
    for (int t = 0; t < l; ++t) f = cmul(f, mi);
    for (int i = 0; i < n * n; ++i) q[i] = cmul(q[i], f);
}

constexpr void wigner3j(int l1, int l2, int l3, double* outv)
{
    const int n1 = 2 * l1 + 1, n2 = 2 * l2 + 1, n3 = 2 * l3 + 1;
    double csu2[225] = {};
    for (int m1 = -l1; m1 <= l1; ++m1)
        for (int m2 = -l2; m2 <= l2; ++m2) {
            int m3 = m1 + m2;
            if (m3 >= -l3 && m3 <= l3)
                csu2[((l1 + m1) * n2 + (l2 + m2)) * n3 + (l3 + m3)] =
                    su2cg(l1, m1, l2, m2, l3, m3);
        }
    CD q1[81] = {}, q2[25] = {}, q3[25] = {};
    qmat(l1, q1); qmat(l2, q2); qmat(l3, q3);

    CD cc[225] = {};
    for (int i = 0; i < n1 * n2 * n3; ++i) cc[i] = {0.0, 0.0};
    for (int i = 0; i < n1; ++i)
        for (int k = 0; k < n2; ++k)
            for (int n = 0; n < n3; ++n) {
                double s = csu2[(i * n2 + k) * n3 + n];
                if (s == 0.0) continue;
                for (int a = 0; a < n1; ++a) {
                    CD qa = q1[i * n1 + a];
                    if (czero(qa)) continue;
                    for (int b = 0; b < n2; ++b) {
                        CD qb = q2[k * n2 + b];
                        if (czero(qb)) continue;
                        CD qab = cmul(qa, qb);
                        qab.re *= s; qab.im *= s;
                        for (int c = 0; c < n3; ++c) {
                            CD q3c = q3[n * n3 + c];
                            if (czero(q3c)) continue;
                            CD cj{q3c.re, -q3c.im};
                            CD add = cmul(qab, cj);
                            cc[(a * n2 + b) * n3 + c].re += add.re;
                            cc[(a * n2 + b) * n3 + c].im += add.im;
                        }
                    }
                }
            }
    double nre = 0.0, nim = 0.0;
    for (int i = 0; i < n1 * n2 * n3; ++i) {
        nre += cc[i].re * cc[i].re;
        nim += cc[i].im * cc[i].im;
    }
    bool useRe = csqrt(nre) >= csqrt(nim);
    double nn = csqrt(useRe ? nre : nim);
    for (int i = 0; i < n1 * n2 * n3; ++i)
        outv[i] = (useRe ? cc[i].re : cc[i].im) / nn;
}

// -------------------- pair-unit table --------------------
struct PTab {
    int   ncols[36];          // columns per pair (= nr*nc)
    int   coloff[36][25];     // xs word offsets (col * XST)
    int   nrows[36];          // output rows per pair
    int   rowid[36][25];      // natural output row ids
    int   nterm[36][25];
    float tc[36][25][25];     // coefficients
    int   tk[36][25][25];     // local column index
    int   wp[NWARP][12];      // warp -> pair list
    int   nwp[NWARP];
};

constexpr PTab build()
{
    PTab T{};
    const int LSh[6]  = {0, 0, 0, 1, 1, 2};
    const int IDXC[NAO] = {0, 1, 2, 5, 3, 4, 8, 6, 7, 11, 13, 9, 12, 10};
    int inv[NAO] = {};
    for (int i = 0; i < NAO; ++i) inv[IDXC[i]] = i;

    // enumerate blocks (original order) with pair id
    int brs[56] = {}, bnr[56] = {}, bcs[56] = {}, bnc[56] = {}, bL[56] = {}, bpar[56] = {}, bco[56] = {}, bp[56] = {};
    double cg[2120] = {};
    int nb = 0, cgo = 0, rs = 0;
    for (int a = 0; a < 6; ++a) {
        int li = LSh[a], nr = 2 * li + 1, cs = 0;
        for (int b = 0; b < 6; ++b) {
            int lj = LSh[b], nc = 2 * lj + 1;
            int L0 = li > lj ? li - lj : lj - li;
            for (int L = L0; L <= li + lj; ++L) {
                brs[nb] = rs; bnr[nb] = nr; bcs[nb] = cs; bnc[nb] = nc;
                bL[nb] = L; bpar[nb] = ((li + lj) & 1) ? -1 : 1; bco[nb] = cgo;
                bp[nb] = a * 6 + b;
                wigner3j(L, li, lj, &cg[cgo]);
                cgo += (2 * L + 1) * nr * nc;
                ++nb;
            }
            cs += nc;
        }
        rs += nr;
    }

    // stable sort of blocks by (L, parity) -> output layout
    int perm[56] = {};
    for (int i = 0; i < 56; ++i) perm[i] = i;
    for (int i = 1; i < 56; ++i) {
        int p = perm[i]; int j = i - 1;
        while (j >= 0 && (bL[perm[j]] > bL[p] ||
               (bL[perm[j]] == bL[p] && bpar[perm[j]] > bpar[p]))) {
            perm[j + 1] = perm[j]; --j;
        }
        perm[j + 1] = p;
    }
    int outbase[56] = {};
    { int base = 0; for (int t = 0; t < 56; ++t) { outbase[perm[t]] = base; base += 2 * bL[perm[t]] + 1; } }

    // pair columns
    {
        int prs = 0;
        for (int a = 0; a < 6; ++a) {
            int li = LSh[a], nr = 2 * li + 1, pcs = 0;
            for (int b = 0; b < 6; ++b) {
                int lj = LSh[b], nc = 2 * lj + 1;
                int p = a * 6 + b;
                T.ncols[p] = nr * nc;
                for (int i = 0; i < nr; ++i)
                    for (int j = 0; j < nc; ++j) {
                        int col = inv[prs + i] * NAO + inv[pcs + j];
                        T.coloff[p][i * nc + j] = col * XST;
                    }
                pcs += nc;
            }
            prs += nr;
        }
    }

    // pair rows + terms
    for (int bi = 0; bi < nb; ++bi) {
        int p = bp[bi];
        int w = 2 * bL[bi] + 1;
        for (int k = 0; k < w; ++k) {
            int r  = outbase[bi] + k;
            int ri = T.nrows[p];
            T.rowid[p][ri] = r;
            int nt = 0;
            for (int i = 0; i < bnr[bi]; ++i)
                for (int j = 0; j < bnc[bi]; ++j) {
                    double v = cg[bco[bi] + (k * bnr[bi] + i) * bnc[bi] + j];
                    double av = v < 0 ? -v : v;
                    if (av > 1e-9) {
                        T.tc[p][ri][nt] = (float)v;
                        T.tk[p][ri][nt] = i * bnc[bi] + j;
                        ++nt;
                    }
                }
            T.nterm[p][ri] = nt;
            T.nrows[p]++;
        }
    }

    // pair cost & greedy warp assignment (sorted by cost desc, stable)
    int cost[36] = {};
    for (int p = 0; p < 36; ++p) {
        int c = T.ncols[p] + T.nrows[p];
        for (int r = 0; r < T.nrows[p]; ++r) c += T.nterm[p][r];
        cost[p] = c;
    }
    int order[36] = {};
    for (int i = 0; i < 36; ++i) order[i] = i;
    for (int i = 1; i < 36; ++i) {
        int p = order[i]; int j = i - 1;
        while (j >= 0 && cost[order[j]] < cost[p]) { order[j + 1] = order[j]; --j; }
        order[j + 1] = p;
    }
    int wcost[NWARP] = {};
    for (int i = 0; i < 36; ++i) {
        int best = 0;
        for (int w = 1; w < NWARP; ++w) if (wcost[w] < wcost[best]) best = w;
        T.wp[best][T.nwp[best]] = order[i];
        T.nwp[best]++;
        wcost[best] += cost[order[i]];
    }
    return T;
}

constexpr PTab PT = build();

} // namespace ct

// ===========================================================================
// Fully-unrolled compute. Every table access is hoisted into a constexpr
// local so only compile-time immediates reach device code.
// ===========================================================================
template<int P, int K>
__device__ __forceinline__ void load_cols(const float* xl, float* v)
{
    constexpr int o  = ct::PT.coloff[P][K];
    constexpr int nc = ct::PT.ncols[P];
    v[K] = xl[o];
    if constexpr (K + 1 < nc) load_cols<P, K + 1>(xl, v);
}

template<int P, int R, int T>
__device__ __forceinline__ void row_terms(const float* v, float& a)
{
    constexpr float c  = ct::PT.tc[P][R][T];
    constexpr int   k  = ct::PT.tk[P][R][T];
    constexpr int   nt = ct::PT.nterm[P][R];
    a = fmaf(c, v[k], a);
    if constexpr (T + 1 < nt) row_terms<P, R, T + 1>(v, a);
}

template<int P, int R>
__device__ __forceinline__ void pair_rows(const float* v, float* os, int lane)
{
    constexpr int nt = ct::PT.nterm[P][R];
    constexpr int ro = ct::PT.rowid[P][R] * XST;
    constexpr int nr = ct::PT.nrows[P];
    float a = 0.f;
    if constexpr (nt > 0) row_terms<P, R, 0>(v, a);
    os[ro + lane] = a;
    if constexpr (R + 1 < nr) pair_rows<P, R + 1>(v, os, lane);
}

template<int P>
__device__ __forceinline__ void pair_run(const float* xl, float* os, int lane)
{
    float v[25];
    load_cols<P, 0>(xl, v);
    pair_rows<P, 0>(v, os, lane);
}

template<int W, int I>
__device__ __forceinline__ void warp_run(const float* xl, float* os, int lane)
{
    constexpr int p  = ct::PT.wp[W][I];
    constexpr int np = ct::PT.nwp[W];
    pair_run<p>(xl, os, lane);
    if constexpr (I + 1 < np) warp_run<W, I + 1>(xl, os, lane);
}

__global__ void __launch_bounds__(NTHR, 4)
te_kernel(const float* __restrict__ x, float* __restrict__ out, int nsamp)
{
    extern __shared__ float sm[];
    float* xs = sm;                  // [196][33]  element-major, sample fastest
    float* os = sm + NAO2 * XST;     // [196][33]

    const int tid  = threadIdx.x;
    const int wid  = tid >> 5;
    const int lane = tid & 31;
    const int n0   = blockIdx.x * SPB;

    // ---- stage in: warp w owns samples w, w+8, w+16, w+24 ----
    // Affine addressing: LDG coalesced within the sample row; STS lane-stride
    // XST = 33 == 1 (mod 32) -> conflict-free. No div/mod/wrap arithmetic.
    #pragma unroll
    for (int q = 0; q < 4; ++q) {
        const int s = wid + q * NWARP;
        if (n0 + s < nsamp) {
            const float* src  = x + (long long)(n0 + s) * NAO2;
            float*       dstp = xs + s + lane * XST;
            #pragma unroll
            for (int i = 0; i < 6; ++i)
                dstp[i * 32 * XST] = src[lane + i * 32];
            if (lane < 4)
                dstp[6 * 32 * XST] = src[lane + 192];
        }
    }
    __syncthreads();

    // ---- pair-structured, fully-unrolled sparse matvec ----
    {
        const float* xl = xs + lane;
        switch (wid) {
            case 0:  warp_run<0, 0>(xl, os, lane); break;
            case 1:  warp_run<1, 0>(xl, os, lane); break;
            case 2:  warp_run<2, 0>(xl, os, lane); break;
            case 3:  warp_run<3, 0>(xl, os, lane); break;
            case 4:  warp_run<4, 0>(xl, os, lane); break;
            case 5:  warp_run<5, 0>(xl, os, lane); break;
            case 6:  warp_run<6, 0>(xl, os, lane); break;
            default: warp_run<7, 0>(xl, os, lane); break;
        }
    }
    __syncthreads();

    // ---- stage out: symmetric (LDS conflict-free, STG coalesced) ----
    #pragma unroll
    for (int q = 0; q < 4; ++q) {
        const int s = wid + q * NWARP;
        if (n0 + s < nsamp) {
            float*       dst  = out + (long long)(n0 + s) * NAO2;
            const float* srcp = os + s + lane * XST;
            #pragma unroll
            for (int i = 0; i < 6; ++i)
                dst[lane + i * 32] = srcp[i * 32 * XST];
            if (lane < 4)
                dst[lane + 192] = srcp[6 * 32 * XST];
        }
    }
}

extern "C" void kernel_launch(void* const* d_in, const int* in_sizes, int n_in,
                              void* d_out, int out_size)
{
    (void)n_in; (void)out_size;
    const float* x  = (const float*)d_in[0];
    float*      out = (float*)d_out;
    const int nsamp = in_sizes[0] / NAO2;

    cudaFuncSetAttribute(te_kernel, cudaFuncAttributeMaxDynamicSharedMemorySize, SMEM_BYTES);

    const int grid = (nsamp + SPB - 1) / SPB;
    te_kernel<<<grid, NTHR, SMEM_BYTES>>>(x, out, nsamp);
}

// round 13
// speedup vs baseline: 1.4416x; 1.1261x over previous
#include <cuda_runtime.h>

#define NAO   14
#define NAO2  196
#define SPB   32            // samples per block
#define XST   33            // smem word stride (odd -> conflict-free)
#define NTHR  256
#define NWARP 8
#define SMEM_BYTES (NAO2 * XST * 4)   // single in-place buffer

// ===========================================================================
// Compile-time construction of the CG / Wigner-3j sparse matrix, organised
// as 36 orbital-pair units. Each input column belongs to exactly one pair,
// so warps own disjoint column sets -> in-place smem reuse is safe with one
// barrier between "all columns read" and "rows written".
// ===========================================================================
namespace ct {

constexpr double fct(int n) { double r = 1.0; for (int i = 2; i <= n; ++i) r *= i; return r; }

constexpr double csqrt(double v)
{
    if (v <= 0.0) return 0.0;
    double x = v < 1.0 ? 1.0 : v;
    for (int i = 0; i < 100; ++i) {
        double nx = 0.5 * (x + v / x);
        if (nx == x) break;
        x = nx;
    }
    return x;
}

constexpr double su2cg(int j1, int m1, int j2, int m2, int j3, int m3)
{
    if (m3 != m1 + m2) return 0.0;
    int vmin = -j1 + j2 + m3; if (-j1 + m1 > vmin) vmin = -j1 + m1; if (0 > vmin) vmin = 0;
    int vmax = j2 + j3 + m1; if (j3 - j1 + j2 < vmax) vmax = j3 - j1 + j2; if (j3 + m3 < vmax) vmax = j3 + m3;
    double c = csqrt((2.0 * j3 + 1) * fct(j3 + j1 - j2) * fct(j3 - j1 + j2) *
                     fct(j1 + j2 - j3) * fct(j3 + m3) * fct(j3 - m3) /
                     (fct(j1 + j2 + j3 + 1) * fct(j1 - m1) * fct(j1 + m1) *
                      fct(j2 - m2) * fct(j2 + m2)));
    double s = 0.0;
    for (int v = vmin; v <= vmax; ++v) {
        double sign = ((v + j2 + m2) & 1) ? -1.0 : 1.0;
        s += sign * fct(j2 + j3 + m1 - v) * fct(j1 - m1 + v) /
             (fct(v) * fct(j3 - j1 + j2 - v) * fct(j3 + m3 - v) * fct(v + j1 - j2 - m3));
    }
    return c * s;
}

struct CD { double re; double im; };
constexpr CD cmul(CD a, CD b) { return {a.re * b.re - a.im * b.im, a.re * b.im + a.im * b.re}; }
constexpr bool czero(CD a) { return a.re == 0.0 && a.im == 0.0; }

constexpr void qmat(int l, CD* q)
{
    int n = 2 * l + 1;
    for (int i = 0; i < n * n; ++i) q[i] = {0.0, 0.0};
    double is2 = csqrt(0.5);
    for (int m = -l; m < 0; ++m) {
        q[(l + m) * n + (l - m)] = {is2, 0.0};
        q[(l + m) * n + (l + m)] = {0.0, -is2};
    }
    q[l * n + l] = {1.0, 0.0};
    for (int m = 1; m <= l; ++m) {
        double sg = (m & 1) ? -1.0 : 1.0;
        q[(l + m) * n + (l + m)] = {sg * is2, 0.0};
        q[(l + m) * n + (l - m)] = {0.0, sg * is2};
    }
    CD f{1.0, 0.0};
    const CD mi{0.0, -1.0};
    for (int t = 0; t < l; ++t) f = cmul(f, mi);
    for (int i = 0; i < n * n; ++i) q[i] = cmul(q[i], f);
}

constexpr void wigner3j(int l1, int l2, int l3, double* outv)
{
    const int n1 = 2 * l1 + 1, n2 = 2 * l2 + 1, n3 = 2 * l3 + 1;
    double csu2[225] = {};
    for (int m1 = -l1; m1 <= l1; ++m1)
        for (int m2 = -l2; m2 <= l2; ++m2) {
            int m3 = m1 + m2;
            if (m3 >= -l3 && m3 <= l3)
                csu2[((l1 + m1) * n2 + (l2 + m2)) * n3 + (l3 + m3)] =
                    su2cg(l1, m1, l2, m2, l3, m3);
        }
    CD q1[81] = {}, q2[25] = {}, q3[25] = {};
    qmat(l1, q1); qmat(l2, q2); qmat(l3, q3);

    CD cc[225] = {};
    for (int i = 0; i < n1 * n2 * n3; ++i) cc[i] = {0.0, 0.0};
    for (int i = 0; i < n1; ++i)
        for (int k = 0; k < n2; ++k)
            for (int n = 0; n < n3; ++n) {
                double s = csu2[(i * n2 + k) * n3 + n];
                if (s == 0.0) continue;
                for (int a = 0; a < n1; ++a) {
                    CD qa = q1[i * n1 + a];
                    if (czero(qa)) continue;
                    for (int b = 0; b < n2; ++b) {
                        CD qb = q2[k * n2 + b];
                        if (czero(qb)) continue;
                        CD qab = cmul(qa, qb);
                        qab.re *= s; qab.im *= s;
                        for (int c = 0; c < n3; ++c) {
                            CD q3c = q3[n * n3 + c];
                            if (czero(q3c)) continue;
                            CD cj{q3c.re, -q3c.im};
                            CD add = cmul(qab, cj);
                            cc[(a * n2 + b) * n3 + c].re += add.re;
                            cc[(a * n2 + b) * n3 + c].im += add.im;
                        }
                    }
                }
            }
    double nre = 0.0, nim = 0.0;
    for (int i = 0; i < n1 * n2 * n3; ++i) {
        nre += cc[i].re * cc[i].re;
        nim += cc[i].im * cc[i].im;
    }
    bool useRe = csqrt(nre) >= csqrt(nim);
    double nn = csqrt(useRe ? nre : nim);
    for (int i = 0; i < n1 * n2 * n3; ++i)
        outv[i] = (useRe ? cc[i].re : cc[i].im) / nn;
}

// -------------------- pair-unit table --------------------
struct PTab {
    int   ncols[36];          // columns per pair (= nr*nc)
    int   coloff[36][25];     // xs word offsets (col * XST)
    int   nrows[36];          // output rows per pair
    int   rowid[36][25];      // natural output row ids
    int   nterm[36][25];
    float tc[36][25][25];     // coefficients
    int   tk[36][25][25];     // local column index
    int   wp[NWARP][12];      // warp -> pair list
    int   wcb[NWARP][12];     // per-warp register-file base of each pair's cols
    int   nwp[NWARP];
};

constexpr PTab build()
{
    PTab T{};
    const int LSh[6]  = {0, 0, 0, 1, 1, 2};
    const int IDXC[NAO] = {0, 1, 2, 5, 3, 4, 8, 6, 7, 11, 13, 9, 12, 10};
    int inv[NAO] = {};
    for (int i = 0; i < NAO; ++i) inv[IDXC[i]] = i;

    // enumerate blocks (original order) with pair id
    int brs[56] = {}, bnr[56] = {}, bcs[56] = {}, bnc[56] = {}, bL[56] = {}, bpar[56] = {}, bco[56] = {}, bp[56] = {};
    double cg[2120] = {};
    int nb = 0, cgo = 0, rs = 0;
    for (int a = 0; a < 6; ++a) {
        int li = LSh[a], nr = 2 * li + 1, cs = 0;
        for (int b = 0; b < 6; ++b) {
            int lj = LSh[b], nc = 2 * lj + 1;
            int L0 = li > lj ? li - lj : lj - li;
            for (int L = L0; L <= li + lj; ++L) {
                brs[nb] = rs; bnr[nb] = nr; bcs[nb] = cs; bnc[nb] = nc;
                bL[nb] = L; bpar[nb] = ((li + lj) & 1) ? -1 : 1; bco[nb] = cgo;
                bp[nb] = a * 6 + b;
                wigner3j(L, li, lj, &cg[cgo]);
                cgo += (2 * L + 1) * nr * nc;
                ++nb;
            }
            cs += nc;
        }
        rs += nr;
    }

    // stable sort of blocks by (L, parity) -> output layout
    int perm[56] = {};
    for (int i = 0; i < 56; ++i) perm[i] = i;
    for (int i = 1; i < 56; ++i) {
        int p = perm[i]; int j = i - 1;
        while (j >= 0 && (bL[perm[j]] > bL[p] ||
               (bL[perm[j]] == bL[p] && bpar[perm[j]] > bpar[p]))) {
            perm[j + 1] = perm[j]; --j;
        }
        perm[j + 1] = p;
    }
    int outbase[56] = {};
    { int base = 0; for (int t = 0; t < 56; ++t) { outbase[perm[t]] = base; base += 2 * bL[perm[t]] + 1; } }

    // pair columns
    {
        int prs = 0;
        for (int a = 0; a < 6; ++a) {
            int li = LSh[a], nr = 2 * li + 1, pcs = 0;
            for (int b = 0; b < 6; ++b) {
                int lj = LSh[b], nc = 2 * lj + 1;
                int p = a * 6 + b;
                T.ncols[p] = nr * nc;
                for (int i = 0; i < nr; ++i)
                    for (int j = 0; j < nc; ++j) {
                        int col = inv[prs + i] * NAO + inv[pcs + j];
                        T.coloff[p][i * nc + j] = col * XST;
                    }
                pcs += nc;
            }
            prs += nr;
        }
    }

    // pair rows + terms
    for (int bi = 0; bi < nb; ++bi) {
        int p = bp[bi];
        int w = 2 * bL[bi] + 1;
        for (int k = 0; k < w; ++k) {
            int r  = outbase[bi] + k;
            int ri = T.nrows[p];
            T.rowid[p][ri] = r;
            int nt = 0;
            for (int i = 0; i < bnr[bi]; ++i)
                for (int j = 0; j < bnc[bi]; ++j) {
                    double v = cg[bco[bi] + (k * bnr[bi] + i) * bnc[bi] + j];
                    double av = v < 0 ? -v : v;
                    if (av > 1e-9) {
                        T.tc[p][ri][nt] = (float)v;
                        T.tk[p][ri][nt] = i * bnc[bi] + j;
                        ++nt;
                    }
                }
            T.nterm[p][ri] = nt;
            T.nrows[p]++;
        }
    }

    // pair cost & greedy warp assignment (sorted by cost desc, stable)
    int cost[36] = {};
    for (int p = 0; p < 36; ++p) {
        int c = T.ncols[p] + T.nrows[p];
        for (int r = 0; r < T.nrows[p]; ++r) c += T.nterm[p][r];
        cost[p] = c;
    }
    int order[36] = {};
    for (int i = 0; i < 36; ++i) order[i] = i;
    for (int i = 1; i < 36; ++i) {
        int p = order[i]; int j = i - 1;
        while (j >= 0 && cost[order[j]] < cost[p]) { order[j + 1] = order[j]; --j; }
        order[j + 1] = p;
    }
    int wcost[NWARP] = {};
    for (int i = 0; i < 36; ++i) {
        int best = 0;
        for (int w = 1; w < NWARP; ++w) if (wcost[w] < wcost[best]) best = w;
        T.wp[best][T.nwp[best]] = order[i];
        T.nwp[best]++;
        wcost[best] += cost[order[i]];
    }
    // per-warp register-file column bases (prefix sums)
    for (int w = 0; w < NWARP; ++w) {
        int base = 0;
        for (int i = 0; i < T.nwp[w]; ++i) {
            T.wcb[w][i] = base;
            base += T.ncols[T.wp[w][i]];
        }
    }
    return T;
}

constexpr PTab PT = build();

} // namespace ct

#define MAXC 32   // >= max per-warp total column count (~27)

// ===========================================================================
// Fully-unrolled compute, all table accesses hoisted to constexpr locals.
// Phase A: load every column this warp owns into registers.
// Phase B (after barrier): compute rows and write them in-place.
// ===========================================================================
template<int P, int K, int B>
__device__ __forceinline__ void load_pair_cols(const float* xl, float* v)
{
    constexpr int o  = ct::PT.coloff[P][K];
    constexpr int nc = ct::PT.ncols[P];
    v[B + K] = xl[o];
    if constexpr (K + 1 < nc) load_pair_cols<P, K + 1, B>(xl, v);
}

template<int W, int I>
__device__ __forceinline__ void warp_load(const float* xl, float* v)
{
    constexpr int p  = ct::PT.wp[W][I];
    constexpr int b  = ct::PT.wcb[W][I];
    constexpr int np = ct::PT.nwp[W];
    load_pair_cols<p, 0, b>(xl, v);
    if constexpr (I + 1 < np) warp_load<W, I + 1>(xl, v);
}

template<int P, int R, int T, int B>
__device__ __forceinline__ void row_terms(const float* v, float& a)
{
    constexpr float c  = ct::PT.tc[P][R][T];
    constexpr int   k  = ct::PT.tk[P][R][T];
    constexpr int   nt = ct::PT.nterm[P][R];
    a = fmaf(c, v[B + k], a);
    if constexpr (T + 1 < nt) row_terms<P, R, T + 1, B>(v, a);
}

template<int P, int R, int B>
__device__ __forceinline__ void pair_rows(const float* v, float* os, int lane)
{
    constexpr int nt = ct::PT.nterm[P][R];
    constexpr int ro = ct::PT.rowid[P][R] * XST;
    constexpr int nr = ct::PT.nrows[P];
    float a = 0.f;
    if constexpr (nt > 0) row_terms<P, R, 0, B>(v, a);
    os[ro + lane] = a;
    if constexpr (R + 1 < nr) pair_rows<P, R + 1, B>(v, os, lane);
}

template<int W, int I>
__device__ __forceinline__ void warp_store(const float* v, float* os, int lane)
{
    constexpr int p  = ct::PT.wp[W][I];
    constexpr int b  = ct::PT.wcb[W][I];
    constexpr int np = ct::PT.nwp[W];
    pair_rows<p, 0, b>(v, os, lane);
    if constexpr (I + 1 < np) warp_store<W, I + 1>(v, os, lane);
}

__global__ void __launch_bounds__(NTHR, 6)
te_kernel(const float* __restrict__ x, float* __restrict__ out, int nsamp)
{
    extern __shared__ float sm[];
    float* buf = sm;                 // [196][33]  in-place: xs, then os

    const int tid  = threadIdx.x;
    const int wid  = tid >> 5;
    const int lane = tid & 31;
    const int n0   = blockIdx.x * SPB;

    // ---- stage in: warp w owns samples w, w+8, w+16, w+24 (affine) ----
    #pragma unroll
    for (int q = 0; q < 4; ++q) {
        const int s = wid + q * NWARP;
        if (n0 + s < nsamp) {
            const float* src  = x + (long long)(n0 + s) * NAO2;
            float*       dstp = buf + s + lane * XST;
            #pragma unroll
            for (int i = 0; i < 6; ++i)
                dstp[i * 32 * XST] = src[lane + i * 32];
            if (lane < 4)
                dstp[6 * 32 * XST] = src[lane + 192];
        }
    }
    __syncthreads();

    // ---- phase A: each warp pulls ALL of its columns into registers ----
    float v[MAXC];
    {
        const float* xl = buf + lane;
        switch (wid) {
            case 0:  warp_load<0, 0>(xl, v); break;
            case 1:  warp_load<1, 0>(xl, v); break;
            case 2:  warp_load<2, 0>(xl, v); break;
            case 3:  warp_load<3, 0>(xl, v); break;
            case 4:  warp_load<4, 0>(xl, v); break;
            case 5:  warp_load<5, 0>(xl, v); break;
            case 6:  warp_load<6, 0>(xl, v); break;
            default: warp_load<7, 0>(xl, v); break;
        }
    }
    __syncthreads();   // all reads complete before in-place overwrite

    // ---- phase B: compute rows from registers, write in-place ----
    switch (wid) {
        case 0:  warp_store<0, 0>(v, buf, lane); break;
        case 1:  warp_store<1, 0>(v, buf, lane); break;
        case 2:  warp_store<2, 0>(v, buf, lane); break;
        case 3:  warp_store<3, 0>(v, buf, lane); break;
        case 4:  warp_store<4, 0>(v, buf, lane); break;
        case 5:  warp_store<5, 0>(v, buf, lane); break;
        case 6:  warp_store<6, 0>(v, buf, lane); break;
        default: warp_store<7, 0>(v, buf, lane); break;
    }
    __syncthreads();

    // ---- stage out: symmetric (LDS conflict-free, STG coalesced) ----
    #pragma unroll
    for (int q = 0; q < 4; ++q) {
        const int s = wid + q * NWARP;
        if (n0 + s < nsamp) {
            float*       dst  = out + (long long)(n0 + s) * NAO2;
            const float* srcp = buf + s + lane * XST;
            #pragma unroll
            for (int i = 0; i < 6; ++i)
                dst[lane + i * 32] = srcp[i * 32 * XST];
            if (lane < 4)
                dst[lane + 192] = srcp[6 * 32 * XST];
        }
    }
}

extern "C" void kernel_launch(void* const* d_in, const int* in_sizes, int n_in,
                              void* d_out, int out_size)
{
    (void)n_in; (void)out_size;
    const float* x  = (const float*)d_in[0];
    float*      out = (float*)d_out;
    const int nsamp = in_sizes[0] / NAO2;

    cudaFuncSetAttribute(te_kernel, cudaFuncAttributeMaxDynamicSharedMemorySize, SMEM_BYTES);

    const int grid = (nsamp + SPB - 1) / SPB;
    te_kernel<<<grid, NTHR, SMEM_BYTES>>>(x, out, nsamp);
}